// round 13
// baseline (speedup 1.0000x reference)
#include <cuda_runtime.h>

// Problem constants: N=1, C=4, D=3, H=W=64
#define NELEM 49152      // 4*3*64*64
#define HW    4096
#define PERCH 12288      // D*H*W per channel
#define TMAX  128        // max tiles of 32 per slice (P<=4096)
#define PAIRB 2064       // blocks of 4 warp-pairs per slice (covers T=128: 8256 pairs)

__device__ float  d_vpre[NELEM];
__device__ float  d_kqpre[NELEM];
__device__ float  d_part[16 * 48];     // [quant(4)*chan(4)][48 block partials]
__device__ float  d_v[NELEM];
__device__ float  d_q[NELEM];

// sparsity-compacted state (per slice of 4096)
__device__ int    d_nnz[12];
__device__ int    d_P[12];             // nnz padded up to multiple of 128
__device__ float  d_qnz[NELEM];        // compacted q values (padding = 0)
__device__ int    d_idxnz[NELEM];      // compacted k -> original pos
__device__ int    d_rank[NELEM];       // original pos -> compacted k (nz only)
__device__ float  d_S0[12];            // sum_{zero i} v_i / 4096
__device__ float  d_AnzP[12][16];      // per-block Anz partials (from k_mid)
__device__ float2 d_qanz[NELEM];       // compacted {qln_i, a_i} (padding = {0,0})
__device__ float  d_s1[TMAX * NELEM];  // sym pass1 partials: [opp_tile][row]
__device__ float  d_s2[TMAX * NELEM];  // sym pass2 partials: [opp_tile][row]

__device__ __forceinline__ float ex2f_(float x) {
    float y;
    asm("ex2.approx.f32 %0, %1;" : "=f"(y) : "f"(x));
    return y;
}

#define L2E 1.4426950408889634f

// ---------------------------------------------------------------------------
// K1: conv3x3x3 + bias and conv1x1x1 + bias; per-block stats partials
// ---------------------------------------------------------------------------
__global__ void k_conv(const float* __restrict__ x, const float* __restrict__ W3,
                       const float* __restrict__ b3, const float* __restrict__ W1,
                       const float* __restrict__ b1)
{
    __shared__ float sW3[432], sW1[16], sb3[4], sb1[4];
    int t = threadIdx.x;
    for (int i = t; i < 432; i += 256) sW3[i] = W3[i];
    if (t < 16)  sW1[t] = W1[t];
    if (t < 4) { sb3[t] = b3[t]; sb1[t] = b1[t]; }
    __syncthreads();

    int idx = blockIdx.x * 256 + t;
    int o  = idx / PERCH;
    int r  = idx % PERCH;
    int d  = r >> 12;
    int hw = r & 4095;
    int h  = hw >> 6;
    int w  = hw & 63;

    float acc3 = sb3[o], acc1 = sb1[o];
    #pragma unroll
    for (int i = 0; i < 4; i++) {
        const float* xi = x + i * PERCH;
        acc1 = fmaf(xi[(d << 12) + hw], sW1[o * 4 + i], acc1);
        const float* wk = sW3 + (o * 4 + i) * 27;
        #pragma unroll
        for (int kd = 0; kd < 3; kd++) {
            int zd = d + kd - 1;
            if (zd < 0 || zd > 2) continue;
            #pragma unroll
            for (int kh = 0; kh < 3; kh++) {
                int zh = h + kh - 1;
                if ((unsigned)zh > 63u) continue;
                #pragma unroll
                for (int kw = 0; kw < 3; kw++) {
                    int zw = w + kw - 1;
                    if ((unsigned)zw > 63u) continue;
                    acc3 = fmaf(xi[(zd << 12) + (zh << 6) + zw],
                                wk[kd * 9 + kh * 3 + kw], acc3);
                }
            }
        }
    }
    d_vpre[idx]  = acc3;
    d_kqpre[idx] = acc1;

    float v0 = acc3, v1 = acc3 * acc3, v2 = acc1, v3 = acc1 * acc1;
    #pragma unroll
    for (int off = 16; off; off >>= 1) {
        v0 += __shfl_down_sync(0xffffffffu, v0, off);
        v1 += __shfl_down_sync(0xffffffffu, v1, off);
        v2 += __shfl_down_sync(0xffffffffu, v2, off);
        v3 += __shfl_down_sync(0xffffffffu, v3, off);
    }
    __shared__ float sred[8][4];
    int wid = t >> 5, lane = t & 31;
    if (lane == 0) { sred[wid][0] = v0; sred[wid][1] = v1; sred[wid][2] = v2; sred[wid][3] = v3; }
    __syncthreads();
    if (t == 0) {
        float s0 = 0, s1 = 0, s2 = 0, s3 = 0;
        #pragma unroll
        for (int i = 0; i < 8; i++) { s0 += sred[i][0]; s1 += sred[i][1]; s2 += sred[i][2]; s3 += sred[i][3]; }
        int b2 = blockIdx.x % 48;
        d_part[(0 * 4 + o) * 48 + b2] = s0;
        d_part[(1 * 4 + o) * 48 + b2] = s1;
        d_part[(2 * 4 + o) * 48 + b2] = s2;
        d_part[(3 * 4 + o) * 48 + b2] = s3;
    }
}

// ---------------------------------------------------------------------------
// K2: fused stats + BN/ReLU + compaction. grid 12 x 1024 (block=slice)
// ---------------------------------------------------------------------------
__global__ void k_prep(const float* __restrict__ g3, const float* __restrict__ be3,
                       const float* __restrict__ g1, const float* __restrict__ be1)
{
    __shared__ float scoef[4];
    __shared__ float ssum[4];
    __shared__ int   soff[32];
    __shared__ float sv[32];
    __shared__ int   s_nnz, s_P;

    int s = blockIdx.x, t = threadIdx.x;
    int lane = t & 31, w = t >> 5;
    int c = s / 3;                        // channel
    int sb = s * 4096;
    int pos = t * 4;

    // issue the big loads first (independent of the stats chain)
    float4 pre3 = *(const float4*)(d_vpre  + sb + pos);
    float4 pre1 = *(const float4*)(d_kqpre + sb + pos);

    if (t < 4) {
        const float* p = d_part + (t * 4 + c) * 48;
        float a = 0.f;
        #pragma unroll
        for (int i = 0; i < 48; i++) a += p[i];
        ssum[t] = a;
    }
    __syncthreads();
    if (t == 0) {
        const float inv_n = 1.0f / 12288.0f;
        float m3  = ssum[0] * inv_n;
        float vr3 = ssum[1] * inv_n - m3 * m3;
        float sc3 = g3[c] * rsqrtf(vr3 + 1e-5f);
        float m1  = ssum[2] * inv_n;
        float vr1 = ssum[3] * inv_n - m1 * m1;
        float sc1 = g1[c] * rsqrtf(vr1 + 1e-5f);
        scoef[0] = sc3; scoef[1] = be3[c] - m3 * sc3;
        scoef[2] = sc1; scoef[3] = be1[c] - m1 * sc1;
    }
    __syncthreads();
    float sc3 = scoef[0], sh3 = scoef[1], sc1 = scoef[2], sh1 = scoef[3];

    float4 vv, qv;
    vv.x = fmaxf(fmaf(pre3.x, sc3, sh3), 0.f);
    vv.y = fmaxf(fmaf(pre3.y, sc3, sh3), 0.f);
    vv.z = fmaxf(fmaf(pre3.z, sc3, sh3), 0.f);
    vv.w = fmaxf(fmaf(pre3.w, sc3, sh3), 0.f);
    qv.x = fmaxf(fmaf(pre1.x, sc1, sh1), 0.f);
    qv.y = fmaxf(fmaf(pre1.y, sc1, sh1), 0.f);
    qv.z = fmaxf(fmaf(pre1.z, sc1, sh1), 0.f);
    qv.w = fmaxf(fmaf(pre1.w, sc1, sh1), 0.f);
    *(float4*)(d_v + sb + pos) = vv;
    *(float4*)(d_q + sb + pos) = qv;

    // compaction flags + scans
    int c0 = qv.x > 0.f, c1 = qv.y > 0.f, c2 = qv.z > 0.f, c3 = qv.w > 0.f;
    int cnt = c0 + c1 + c2 + c3;
    float vz = (c0 ? 0.f : vv.x) + (c1 ? 0.f : vv.y)
             + (c2 ? 0.f : vv.z) + (c3 ? 0.f : vv.w);

    int inc = cnt;                        // warp inclusive scan
    #pragma unroll
    for (int off = 1; off < 32; off <<= 1) {
        int n = __shfl_up_sync(0xffffffffu, inc, off);
        if (lane >= off) inc += n;
    }
    float vzr = vz;                       // warp reduce zero-v sum
    #pragma unroll
    for (int off = 16; off; off >>= 1) vzr += __shfl_down_sync(0xffffffffu, vzr, off);
    if (lane == 31) soff[w] = inc;
    if (lane == 0)  sv[w]   = vzr;
    __syncthreads();
    if (t == 0) {                         // serial deterministic warp-offset scan
        int acc = 0; float vacc = 0.f;
        #pragma unroll
        for (int i = 0; i < 32; i++) {
            int tmp = soff[i]; soff[i] = acc; acc += tmp;
            vacc += sv[i];
        }
        s_nnz = acc;
        s_P   = (acc + 127) & ~127;       // pad to multiple of 128
        d_nnz[s]  = acc;
        d_P[s]    = s_P;
        d_S0[s]   = vacc * (1.0f / 4096.0f);
    }
    __syncthreads();
    int k = soff[w] + (inc - cnt);
    if (c0) { d_qnz[sb + k] = qv.x; d_idxnz[sb + k] = pos;     d_rank[sb + pos]     = k; k++; }
    if (c1) { d_qnz[sb + k] = qv.y; d_idxnz[sb + k] = pos + 1; d_rank[sb + pos + 1] = k; k++; }
    if (c2) { d_qnz[sb + k] = qv.z; d_idxnz[sb + k] = pos + 2; d_rank[sb + pos + 2] = k; k++; }
    if (c3) { d_qnz[sb + k] = qv.w; d_idxnz[sb + k] = pos + 3; d_rank[sb + pos + 3] = k; k++; }
    for (int i = s_nnz + t; i < s_P; i += 1024) {
        d_qnz[sb + i]  = 0.f;
        d_qanz[sb + i] = make_float2(0.f, 0.f);
    }
}

// ---------------------------------------------------------------------------
// pair decode: pair p in [0, T(T+1)/2) -> (a,b), a<=b, row-major upper triangle
// off(a) = a*T - a(a-1)/2
// ---------------------------------------------------------------------------
__device__ __forceinline__ void decode_pair(int p, int T, int& a, int& b)
{
    float tq = (float)(2 * T + 1);
    float disc = tq * tq - 8.0f * (float)p;
    int aa = (int)((tq - sqrtf(fmaxf(disc, 0.f))) * 0.5f);
    if (aa > T - 1) aa = T - 1;
    if (aa < 0) aa = 0;
    while (aa > 0 && p < aa * T - ((aa * (aa - 1)) >> 1)) aa--;
    while (p >= (aa + 1) * T - (((aa + 1) * aa) >> 1)) aa++;
    a = aa;
    b = aa + (p - (aa * T - ((aa * (aa - 1)) >> 1)));
}

// ---------------------------------------------------------------------------
// K3: symmetric pass1 — S partials. Each warp: one (a,b) 32x32 tile pair.
// grid 12*PAIRB x 128. E computed once, feeds row and col sums.
// ---------------------------------------------------------------------------
__global__ void k_sym1()
{
    int s  = blockIdx.x / PAIRB;
    int pb = blockIdx.x % PAIRB;
    int t = threadIdx.x, w = t >> 5, lane = t & 31;
    int P = d_P[s], T = P >> 5;
    int pair = pb * 4 + w;
    int npairs = (T * (T + 1)) >> 1;
    if (pair >= npairs) return;
    int a, b;
    decode_pair(pair, T, a, b);
    int sb = s << 12;

    float rQln = d_qnz[sb + a * 32 + lane] * L2E;   // row tile qln (lane=row)
    float cQ   = d_qnz[sb + b * 32 + lane];         // col tile q  (lane=col)
    float colacc = 0.f, rowacc = 0.f;
    bool diag = (a == b);

    #pragma unroll 8
    for (int d = 0; d < 32; d++) {
        int i = (lane + d) & 31;
        float rq = __shfl_sync(0xffffffffu, rQln, i);
        float e  = ex2f_(rq * cQ);                  // E(i, j=lane)
        colacc += e;
        if (!diag) {
            float recv = __shfl_sync(0xffffffffu, e, (lane - d) & 31);
            rowacc += recv;                          // E(lane, j=(lane-d)&31)
        }
    }
    d_s1[a * NELEM + sb + b * 32 + lane] = colacc;
    if (!diag) d_s1[b * NELEM + sb + a * 32 + lane] = rowacc;
}

// ---------------------------------------------------------------------------
// K4: mid — S_k -> a_k, write {qln,a}; block Anz partials. grid 192 x 256
// ---------------------------------------------------------------------------
__global__ void k_mid()
{
    __shared__ float sm[8];
    int blk = blockIdx.x;
    int t = threadIdx.x;
    int idx = blk * 256 + t;
    int s = idx >> 12, k = idx & 4095;
    int sb = s << 12;
    int P = d_P[s], T = P >> 5, nnz = d_nnz[s];

    float a_val = 0.f;
    if (k < nnz) {
        float S = (float)(4096 - P);
        for (int o = 0; o < T; o++) S += d_s1[o * NELEM + sb + k];
        a_val = d_v[sb + d_idxnz[sb + k]] / S;
        d_qanz[sb + k] = make_float2(d_qnz[sb + k] * L2E, a_val);
    } else if (k < P) {
        d_qanz[sb + k] = make_float2(0.f, 0.f);
    }

    // deterministic block reduction of a_val -> Anz partial
    float a = a_val;
    #pragma unroll
    for (int off = 16; off; off >>= 1) a += __shfl_down_sync(0xffffffffu, a, off);
    int w = t >> 5, lane = t & 31;
    if (lane == 0) sm[w] = a;
    __syncthreads();
    if (t == 0) {
        float tot = ((sm[0] + sm[1]) + (sm[2] + sm[3]))
                  + ((sm[4] + sm[5]) + (sm[6] + sm[7]));
        d_AnzP[s][blk & 15] = tot;
    }
}

// ---------------------------------------------------------------------------
// K5: symmetric pass2 — Patt partials. Weighted dual accumulation.
// grid 12*PAIRB x 128
// ---------------------------------------------------------------------------
__global__ void k_sym2()
{
    int s  = blockIdx.x / PAIRB;
    int pb = blockIdx.x % PAIRB;
    int t = threadIdx.x, w = t >> 5, lane = t & 31;
    int P = d_P[s], T = P >> 5;
    int pair = pb * 4 + w;
    int npairs = (T * (T + 1)) >> 1;
    if (pair >= npairs) return;
    int a, b;
    decode_pair(pair, T, a, b);
    int sb = s << 12;

    float2 ra = d_qanz[sb + a * 32 + lane];         // {qln_i, a_i} (lane=row)
    float  cQ = d_qnz[sb + b * 32 + lane];          // q_j (lane=col)
    float  cA = d_qanz[sb + b * 32 + lane].y;       // a_j
    float colacc = 0.f, rowacc = 0.f;
    bool diag = (a == b);

    #pragma unroll 8
    for (int d = 0; d < 32; d++) {
        int i = (lane + d) & 31;
        float rq = __shfl_sync(0xffffffffu, ra.x, i);
        float rA = __shfl_sync(0xffffffffu, ra.y, i);
        float e  = ex2f_(rq * cQ);                  // E(i, j=lane)
        colacc = fmaf(rA, e, colacc);               // Patt_j += a_i E
        if (!diag) {
            float prod = cA * e;                    // a_j E for row i
            float recv = __shfl_sync(0xffffffffu, prod, (lane - d) & 31);
            rowacc += recv;                          // Patt_lane += a_j E(lane,j)
        }
    }
    d_s2[a * NELEM + sb + b * 32 + lane] = colacc;
    if (!diag) d_s2[b * NELEM + sb + a * 32 + lane] = rowacc;
}

// ---------------------------------------------------------------------------
// K6: final — Datt inline + assemble Patt + residual. grid 64 x 256 over (c,hw)
// ---------------------------------------------------------------------------
__global__ void k_final(const float* __restrict__ x, const float* __restrict__ gama,
                        float* __restrict__ out)
{
    int tid = blockIdx.x * 256 + threadIdx.x;   // 0..16383
    int c = tid >> 12, hw = tid & 4095;
    int base = c * PERCH + hw;
    float gm = gama[0];

    float q0 = d_q[base], q1 = d_q[base + HW], q2 = d_q[base + 2 * HW];
    float v0 = d_v[base], v1 = d_v[base + HW], v2 = d_v[base + 2 * HW];

    // depth attention
    float qm = fmaxf(q0, fmaxf(q1, q2));
    float o0 = 0, o1 = 0, o2 = 0;
    {
        float ql = q0 * L2E, nm = -ql * qm;
        float e0 = ex2f_(fmaf(ql, q0, nm)), e1 = ex2f_(fmaf(ql, q1, nm)), e2 = ex2f_(fmaf(ql, q2, nm));
        float w_ = v0 / (e0 + e1 + e2);
        o0 = fmaf(w_, e0, o0); o1 = fmaf(w_, e1, o1); o2 = fmaf(w_, e2, o2);
    }
    {
        float ql = q1 * L2E, nm = -ql * qm;
        float e0 = ex2f_(fmaf(ql, q0, nm)), e1 = ex2f_(fmaf(ql, q1, nm)), e2 = ex2f_(fmaf(ql, q2, nm));
        float w_ = v1 / (e0 + e1 + e2);
        o0 = fmaf(w_, e0, o0); o1 = fmaf(w_, e1, o1); o2 = fmaf(w_, e2, o2);
    }
    {
        float ql = q2 * L2E, nm = -ql * qm;
        float e0 = ex2f_(fmaf(ql, q0, nm)), e1 = ex2f_(fmaf(ql, q1, nm)), e2 = ex2f_(fmaf(ql, q2, nm));
        float w_ = v2 / (e0 + e1 + e2);
        o0 = fmaf(w_, e0, o0); o1 = fmaf(w_, e1, o1); o2 = fmaf(w_, e2, o2);
    }

    float dat[3] = {o0, o1, o2};
    float qd[3]  = {q0, q1, q2};
    #pragma unroll
    for (int d = 0; d < 3; d++) {
        int s = c * 3 + d;
        int sb = s << 12;
        int idx = base + d * HW;
        float patt;
        if (qd[d] > 0.f) {
            int b = sb + d_rank[idx];
            int T = d_P[s] >> 5;
            float p0 = 0.f;
            for (int o = 0; o < T; o++) p0 += d_s2[o * NELEM + b];
            patt = p0;
        } else {
            float p0 = 0.f;
            #pragma unroll
            for (int cc = 0; cc < 16; cc++) p0 += d_AnzP[s][cc];
            patt = p0;
        }
        patt += d_S0[s];
        out[idx] = fmaf(gm, patt + dat[d], x[idx]);
    }
}

// ---------------------------------------------------------------------------
extern "C" void kernel_launch(void* const* d_in, const int* in_sizes, int n_in,
                              void* d_out, int out_size)
{
    const float* x    = (const float*)d_in[0];
    const float* W3   = (const float*)d_in[1];
    const float* b3   = (const float*)d_in[2];
    const float* g3   = (const float*)d_in[3];
    const float* be3  = (const float*)d_in[4];
    const float* W1   = (const float*)d_in[5];
    const float* b1   = (const float*)d_in[6];
    const float* g1   = (const float*)d_in[7];
    const float* be1  = (const float*)d_in[8];
    const float* gama = (const float*)d_in[9];
    float* out = (float*)d_out;

    k_conv <<<192,  256>>>(x, W3, b3, W1, b1);
    k_prep <<<12,  1024>>>(g3, be3, g1, be1);
    k_sym1 <<<12 * PAIRB, 128>>>();
    k_mid  <<<192,  256>>>();
    k_sym2 <<<12 * PAIRB, 128>>>();
    k_final<<<64,   256>>>(x, gama, out);
}

// round 14
// speedup vs baseline: 1.3592x; 1.3592x over previous
#include <cuda_runtime.h>

// Problem constants: N=1, C=4, D=3, H=W=64
#define NELEM 49152      // 4*3*64*64
#define HW    4096
#define PERCH 12288      // D*H*W per channel

__device__ float  d_vpre[NELEM];
__device__ float  d_kqpre[NELEM];
__device__ float  d_part[16 * 48];     // [quant(4)*chan(4)][48 block partials]
__device__ float  d_v[NELEM];
__device__ float  d_q[NELEM];

// sparsity-compacted state (per slice of 4096)
__device__ int    d_nnz[12];
__device__ int    d_P[12];             // nnz padded up to multiple of 256
__device__ float  d_qnz[NELEM];        // compacted q values (padding = 0)
__device__ int    d_idxnz[NELEM];      // compacted k -> original pos
__device__ int    d_rank[NELEM];       // original pos -> compacted k (nz only)
__device__ float  d_S0[12];            // sum_{zero i} v_i / 4096
__device__ float  d_AnzP[12][32];      // per-chunk Anz partials
__device__ float2 d_qanz[NELEM];       // compacted {qln_i, a_i} (padding = {0,0})
__device__ float  d_ppart[32 * NELEM]; // pass2 chunk partials (compacted idx)

__device__ __forceinline__ float ex2f_(float x) {
    float y;
    asm("ex2.approx.f32 %0, %1;" : "=f"(y) : "f"(x));
    return y;
}

#define L2E 1.4426950408889634f

// ---------------------------------------------------------------------------
// K1: conv3x3x3 + bias and conv1x1x1 + bias; per-block stats partials
// ---------------------------------------------------------------------------
__global__ void k_conv(const float* __restrict__ x, const float* __restrict__ W3,
                       const float* __restrict__ b3, const float* __restrict__ W1,
                       const float* __restrict__ b1)
{
    __shared__ float sW3[432], sW1[16], sb3[4], sb1[4];
    int t = threadIdx.x;
    for (int i = t; i < 432; i += 256) sW3[i] = W3[i];
    if (t < 16)  sW1[t] = W1[t];
    if (t < 4) { sb3[t] = b3[t]; sb1[t] = b1[t]; }
    __syncthreads();

    int idx = blockIdx.x * 256 + t;
    int o  = idx / PERCH;
    int r  = idx % PERCH;
    int d  = r >> 12;
    int hw = r & 4095;
    int h  = hw >> 6;
    int w  = hw & 63;

    float acc3 = sb3[o], acc1 = sb1[o];
    #pragma unroll
    for (int i = 0; i < 4; i++) {
        const float* xi = x + i * PERCH;
        acc1 = fmaf(xi[(d << 12) + hw], sW1[o * 4 + i], acc1);
        const float* wk = sW3 + (o * 4 + i) * 27;
        #pragma unroll
        for (int kd = 0; kd < 3; kd++) {
            int zd = d + kd - 1;
            if (zd < 0 || zd > 2) continue;
            #pragma unroll
            for (int kh = 0; kh < 3; kh++) {
                int zh = h + kh - 1;
                if ((unsigned)zh > 63u) continue;
                #pragma unroll
                for (int kw = 0; kw < 3; kw++) {
                    int zw = w + kw - 1;
                    if ((unsigned)zw > 63u) continue;
                    acc3 = fmaf(xi[(zd << 12) + (zh << 6) + zw],
                                wk[kd * 9 + kh * 3 + kw], acc3);
                }
            }
        }
    }
    d_vpre[idx]  = acc3;
    d_kqpre[idx] = acc1;

    float v0 = acc3, v1 = acc3 * acc3, v2 = acc1, v3 = acc1 * acc1;
    #pragma unroll
    for (int off = 16; off; off >>= 1) {
        v0 += __shfl_down_sync(0xffffffffu, v0, off);
        v1 += __shfl_down_sync(0xffffffffu, v1, off);
        v2 += __shfl_down_sync(0xffffffffu, v2, off);
        v3 += __shfl_down_sync(0xffffffffu, v3, off);
    }
    __shared__ float sred[8][4];
    int wid = t >> 5, lane = t & 31;
    if (lane == 0) { sred[wid][0] = v0; sred[wid][1] = v1; sred[wid][2] = v2; sred[wid][3] = v3; }
    __syncthreads();
    if (t == 0) {
        float s0 = 0, s1 = 0, s2 = 0, s3 = 0;
        #pragma unroll
        for (int i = 0; i < 8; i++) { s0 += sred[i][0]; s1 += sred[i][1]; s2 += sred[i][2]; s3 += sred[i][3]; }
        int b2 = blockIdx.x % 48;
        d_part[(0 * 4 + o) * 48 + b2] = s0;
        d_part[(1 * 4 + o) * 48 + b2] = s1;
        d_part[(2 * 4 + o) * 48 + b2] = s2;
        d_part[(3 * 4 + o) * 48 + b2] = s3;
    }
}

// ---------------------------------------------------------------------------
// K2: fused stats + BN/ReLU + compaction. grid 12 x 1024 (block=slice)
// ---------------------------------------------------------------------------
__global__ void k_prep(const float* __restrict__ g3, const float* __restrict__ be3,
                       const float* __restrict__ g1, const float* __restrict__ be1)
{
    __shared__ float scoef[4];            // {sc3, sh3, sc1, sh1} for this channel
    __shared__ float ssum[4];
    __shared__ int   soff[32];
    __shared__ float sv[32];
    __shared__ int   s_nnz, s_P;

    int s = blockIdx.x, t = threadIdx.x;
    int lane = t & 31, w = t >> 5;
    int c = s / 3;                        // channel
    int sb = s * 4096;
    int pos = t * 4;

    // issue the big loads FIRST (independent of the stats chain)
    float4 pre3 = *(const float4*)(d_vpre  + sb + pos);
    float4 pre1 = *(const float4*)(d_kqpre + sb + pos);

    // zero-init Anz partials in parallel (pass2 overwrites occupied chunks)
    if (s == 0 && t < 384) ((float*)d_AnzP)[t] = 0.f;

    // BN stats: threads 0..3 each reduce 48 partials for quantity t of channel c
    if (t < 4) {
        const float* p = d_part + (t * 4 + c) * 48;
        float a = 0.f;
        #pragma unroll
        for (int i = 0; i < 48; i++) a += p[i];
        ssum[t] = a;
    }
    __syncthreads();
    if (t == 0) {
        const float inv_n = 1.0f / 12288.0f;
        float m3  = ssum[0] * inv_n;
        float vr3 = ssum[1] * inv_n - m3 * m3;
        float sc3 = g3[c] * rsqrtf(vr3 + 1e-5f);
        float m1  = ssum[2] * inv_n;
        float vr1 = ssum[3] * inv_n - m1 * m1;
        float sc1 = g1[c] * rsqrtf(vr1 + 1e-5f);
        scoef[0] = sc3; scoef[1] = be3[c] - m3 * sc3;
        scoef[2] = sc1; scoef[3] = be1[c] - m1 * sc1;
    }
    __syncthreads();
    float sc3 = scoef[0], sh3 = scoef[1], sc1 = scoef[2], sh1 = scoef[3];

    float4 vv, qv;
    vv.x = fmaxf(fmaf(pre3.x, sc3, sh3), 0.f);
    vv.y = fmaxf(fmaf(pre3.y, sc3, sh3), 0.f);
    vv.z = fmaxf(fmaf(pre3.z, sc3, sh3), 0.f);
    vv.w = fmaxf(fmaf(pre3.w, sc3, sh3), 0.f);
    qv.x = fmaxf(fmaf(pre1.x, sc1, sh1), 0.f);
    qv.y = fmaxf(fmaf(pre1.y, sc1, sh1), 0.f);
    qv.z = fmaxf(fmaf(pre1.z, sc1, sh1), 0.f);
    qv.w = fmaxf(fmaf(pre1.w, sc1, sh1), 0.f);
    *(float4*)(d_v + sb + pos) = vv;
    *(float4*)(d_q + sb + pos) = qv;

    // compaction flags + scans
    int c0 = qv.x > 0.f, c1 = qv.y > 0.f, c2 = qv.z > 0.f, c3 = qv.w > 0.f;
    int cnt = c0 + c1 + c2 + c3;
    float vz = (c0 ? 0.f : vv.x) + (c1 ? 0.f : vv.y)
             + (c2 ? 0.f : vv.z) + (c3 ? 0.f : vv.w);

    int inc = cnt;                        // warp inclusive scan
    #pragma unroll
    for (int off = 1; off < 32; off <<= 1) {
        int n = __shfl_up_sync(0xffffffffu, inc, off);
        if (lane >= off) inc += n;
    }
    float vzr = vz;                       // warp reduce zero-v sum
    #pragma unroll
    for (int off = 16; off; off >>= 1) vzr += __shfl_down_sync(0xffffffffu, vzr, off);
    if (lane == 31) soff[w] = inc;
    if (lane == 0)  sv[w]   = vzr;
    __syncthreads();
    if (t == 0) {                         // serial deterministic warp-offset scan
        int acc = 0; float vacc = 0.f;
        #pragma unroll
        for (int i = 0; i < 32; i++) {
            int tmp = soff[i]; soff[i] = acc; acc += tmp;
            vacc += sv[i];
        }
        s_nnz = acc;
        s_P   = (acc + 255) & ~255;       // pad to multiple of 256 (32 chunks keep 8-acc loop)
        d_nnz[s]  = acc;
        d_P[s]    = s_P;
        d_S0[s]   = vacc * (1.0f / 4096.0f);
    }
    __syncthreads();
    int k = soff[w] + (inc - cnt);
    if (c0) { d_qnz[sb + k] = qv.x; d_idxnz[sb + k] = pos;     d_rank[sb + pos]     = k; k++; }
    if (c1) { d_qnz[sb + k] = qv.y; d_idxnz[sb + k] = pos + 1; d_rank[sb + pos + 1] = k; k++; }
    if (c2) { d_qnz[sb + k] = qv.z; d_idxnz[sb + k] = pos + 2; d_rank[sb + pos + 2] = k; k++; }
    if (c3) { d_qnz[sb + k] = qv.w; d_idxnz[sb + k] = pos + 3; d_rank[sb + pos + 3] = k; k++; }
    for (int i = s_nnz + t; i < s_P; i += 1024) {
        d_qnz[sb + i]  = 0.f;
        d_qanz[sb + i] = make_float2(0.f, 0.f);
    }
}

// ---------------------------------------------------------------------------
// K3: pass1: 1 row/lane, 32 rows/block, 8 warp-chunks, pointer-marching inner.
// grid 1536 x 256: slice = blk>>7, rowgroup(32) = blk&127, chunk = warp
// ---------------------------------------------------------------------------
__global__ void k_pass1()
{
    int s = blockIdx.x >> 7;
    int g = blockIdx.x & 127;
    int nnz = d_nnz[s];
    if (g * 32 >= nnz) return;
    __shared__ float sq[4096];
    __shared__ float partZ[8][32];
    int t = threadIdx.x, w = t >> 5, lane = t & 31;
    int sb = s << 12;
    int P  = d_P[s];
    int P4 = P >> 2;

    float4* sq4 = (float4*)sq;
    const float4* gq4 = (const float4*)(d_qnz + sb);
    for (int j = t; j < P4; j += 256) sq4[j] = gq4[j];
    __syncthreads();

    int k = g * 32 + lane;
    float qi   = (k < P) ? sq[k] : 0.f;
    float qln  = qi * L2E;

    int P32 = P >> 5;                      // float4s per warp chunk (mult of 8)
    const float4* p = (const float4*)sq + w * P32;
    float z0 = 0, z1 = 0, z2 = 0, z3 = 0;
    float z4 = 0, z5 = 0, z6 = 0, z7 = 0;
    for (int it = P32 >> 1; it > 0; it--, p += 2) {
        float4 qa = p[0];
        float4 qb = p[1];
        z0 += ex2f_(qln * qa.x);
        z1 += ex2f_(qln * qa.y);
        z2 += ex2f_(qln * qa.z);
        z3 += ex2f_(qln * qa.w);
        z4 += ex2f_(qln * qb.x);
        z5 += ex2f_(qln * qb.y);
        z6 += ex2f_(qln * qb.z);
        z7 += ex2f_(qln * qb.w);
    }
    partZ[w][lane] = ((z0 + z1) + (z2 + z3)) + ((z4 + z5) + (z6 + z7));
    __syncthreads();
    if (w == 0 && k < nnz) {
        // unshifted: q>=0 and |qln*q| <= ~30 so 2^x stays in fp32 range;
        // zero/padding cols give 2^0=1, corrected by the (4096-P) term
        float Z = (((partZ[0][lane] + partZ[1][lane]) + (partZ[2][lane] + partZ[3][lane]))
                +  ((partZ[4][lane] + partZ[5][lane]) + (partZ[6][lane] + partZ[7][lane])))
                + (float)(4096 - P);
        int row = d_idxnz[sb + k];
        float av = d_v[sb + row] / Z;
        d_qanz[sb + k] = make_float2(qln, av);
    }
}

// ---------------------------------------------------------------------------
// K4: pass2, 32 i-chunks, 1 row/thread, pointer-marching 8-acc inner.
// grid 12288 x 128: slice = blk>>10; chunk = (blk&1023)&31; rowgroup(128) = (blk&1023)>>5
// ---------------------------------------------------------------------------
__global__ void k_pass2()
{
    int s   = blockIdx.x >> 10;
    int rem = blockIdx.x & 1023;
    int c   = rem & 31;
    int g   = rem >> 5;                    // [0,32)
    int nnz = d_nnz[s];
    if (g * 128 >= nnz) return;
    int P   = d_P[s];
    int P32 = P >> 5;                      // entries per chunk (mult of 8)
    __shared__ float2 sqa[128];            // up to 1 KB
    __shared__ float sanz[4];
    int t = threadIdx.x;
    int sb = s << 12;

    float4* s4 = (float4*)sqa;
    const float4* g4 = (const float4*)(d_qanz + sb + c * P32);
    int nf4 = P32 >> 1;                    // float4s in chunk (mult of 4)
    for (int j = t; j < nf4; j += 128) s4[j] = g4[j];
    __syncthreads();

    // Anz chunk partial (only g==0 blocks; data already in smem)
    if (g == 0) {
        int w = t >> 5, lane = t & 31;
        float a = 0.f;
        for (int i = t; i < P32; i += 128) a += sqa[i].y;
        #pragma unroll
        for (int off = 16; off; off >>= 1) a += __shfl_down_sync(0xffffffffu, a, off);
        if (lane == 0) sanz[w] = a;
    }

    int k = g * 128 + t;
    float qj = d_qnz[sb + ((k < nnz) ? k : 0)];
    float a0 = 0, a1 = 0, a2 = 0, a3 = 0;
    float a4 = 0, a5 = 0, a6 = 0, a7 = 0;
    const float4* p = (const float4*)sqa;
    for (int it = nf4 >> 2; it > 0; it--, p += 4) {
        float4 u0 = p[0];
        float4 u1 = p[1];
        float4 u2 = p[2];
        float4 u3 = p[3];
        a0 = fmaf(u0.y, ex2f_(u0.x * qj), a0);
        a1 = fmaf(u0.w, ex2f_(u0.z * qj), a1);
        a2 = fmaf(u1.y, ex2f_(u1.x * qj), a2);
        a3 = fmaf(u1.w, ex2f_(u1.z * qj), a3);
        a4 = fmaf(u2.y, ex2f_(u2.x * qj), a4);
        a5 = fmaf(u2.w, ex2f_(u2.z * qj), a5);
        a6 = fmaf(u3.y, ex2f_(u3.x * qj), a6);
        a7 = fmaf(u3.w, ex2f_(u3.z * qj), a7);
    }
    if (k < nnz)
        d_ppart[c * NELEM + sb + k] = ((a0 + a1) + (a2 + a3)) + ((a4 + a5) + (a6 + a7));

    if (g == 0) {
        __syncthreads();
        if (t == 0) d_AnzP[s][c] = (sanz[0] + sanz[1]) + (sanz[2] + sanz[3]);
    }
}

// ---------------------------------------------------------------------------
// K5: final — Datt inline + assemble Patt + residual. grid 64 x 256 over (c,hw)
// ---------------------------------------------------------------------------
__global__ void k_final(const float* __restrict__ x, const float* __restrict__ gama,
                        float* __restrict__ out)
{
    int tid = blockIdx.x * 256 + threadIdx.x;   // 0..16383
    int c = tid >> 12, hw = tid & 4095;
    int base = c * PERCH + hw;
    float gm = gama[0];

    float q0 = d_q[base], q1 = d_q[base + HW], q2 = d_q[base + 2 * HW];
    float v0 = d_v[base], v1 = d_v[base + HW], v2 = d_v[base + 2 * HW];

    // depth attention
    float qm = fmaxf(q0, fmaxf(q1, q2));
    float o0 = 0, o1 = 0, o2 = 0;
    {
        float ql = q0 * L2E, nm = -ql * qm;
        float e0 = ex2f_(fmaf(ql, q0, nm)), e1 = ex2f_(fmaf(ql, q1, nm)), e2 = ex2f_(fmaf(ql, q2, nm));
        float w_ = v0 / (e0 + e1 + e2);
        o0 = fmaf(w_, e0, o0); o1 = fmaf(w_, e1, o1); o2 = fmaf(w_, e2, o2);
    }
    {
        float ql = q1 * L2E, nm = -ql * qm;
        float e0 = ex2f_(fmaf(ql, q0, nm)), e1 = ex2f_(fmaf(ql, q1, nm)), e2 = ex2f_(fmaf(ql, q2, nm));
        float w_ = v1 / (e0 + e1 + e2);
        o0 = fmaf(w_, e0, o0); o1 = fmaf(w_, e1, o1); o2 = fmaf(w_, e2, o2);
    }
    {
        float ql = q2 * L2E, nm = -ql * qm;
        float e0 = ex2f_(fmaf(ql, q0, nm)), e1 = ex2f_(fmaf(ql, q1, nm)), e2 = ex2f_(fmaf(ql, q2, nm));
        float w_ = v2 / (e0 + e1 + e2);
        o0 = fmaf(w_, e0, o0); o1 = fmaf(w_, e1, o1); o2 = fmaf(w_, e2, o2);
    }

    float dat[3] = {o0, o1, o2};
    float qd[3]  = {q0, q1, q2};
    #pragma unroll
    for (int d = 0; d < 3; d++) {
        int s = c * 3 + d;
        int idx = base + d * HW;
        float patt;
        if (qd[d] > 0.f) {
            int b = (s << 12) + d_rank[idx];
            float p0 = 0.f;
            #pragma unroll
            for (int cc = 0; cc < 32; cc++) p0 += d_ppart[cc * NELEM + b];
            patt = p0;
        } else {
            float p0 = 0.f;
            #pragma unroll
            for (int cc = 0; cc < 32; cc++) p0 += d_AnzP[s][cc];
            patt = p0;
        }
        patt += d_S0[s];
        out[idx] = fmaf(gm, patt + dat[d], x[idx]);
    }
}

// ---------------------------------------------------------------------------
extern "C" void kernel_launch(void* const* d_in, const int* in_sizes, int n_in,
                              void* d_out, int out_size)
{
    const float* x    = (const float*)d_in[0];
    const float* W3   = (const float*)d_in[1];
    const float* b3   = (const float*)d_in[2];
    const float* g3   = (const float*)d_in[3];
    const float* be3  = (const float*)d_in[4];
    const float* W1   = (const float*)d_in[5];
    const float* b1   = (const float*)d_in[6];
    const float* g1   = (const float*)d_in[7];
    const float* be1  = (const float*)d_in[8];
    const float* gama = (const float*)d_in[9];
    float* out = (float*)d_out;

    k_conv <<<192,  256>>>(x, W3, b3, W1, b1);
    k_prep <<<12,  1024>>>(g3, be3, g1, be1);
    k_pass1<<<1536, 256>>>();
    k_pass2<<<12288, 128>>>();
    k_final<<<64,   256>>>(x, gama, out);
}

// round 15
// speedup vs baseline: 1.4205x; 1.0451x over previous
#include <cuda_runtime.h>

// Problem constants: N=1, C=4, D=3, H=W=64
#define NELEM 49152      // 4*3*64*64
#define HW    4096
#define PERCH 12288      // D*H*W per channel

__device__ float  d_vpre[NELEM];
__device__ float  d_kqpre[NELEM];
__device__ float  d_part[16 * 48];     // [quant(4)*chan(4)][48 block partials]
__device__ float  d_v[NELEM];
__device__ float  d_q[NELEM];

// sparsity-compacted state (per slice of 4096)
__device__ int    d_nnz[12];
__device__ int    d_P[12];             // nnz padded up to multiple of 128
__device__ float  d_qnz[NELEM];        // compacted q values (padding = 0)
__device__ int    d_idxnz[NELEM];      // compacted k -> original pos
__device__ int    d_rank[NELEM];       // original pos -> compacted k (nz only)
__device__ float  d_S0[12];            // sum_{zero i} v_i / 4096
__device__ float  d_AnzP[12][16];      // per-chunk Anz partials
__device__ float2 d_qanz[NELEM];       // compacted {qln_i, a_i} (padding = {0,0})
__device__ float  d_ppart[16 * NELEM]; // pass2 chunk partials (compacted idx)

__device__ __forceinline__ float ex2f_(float x) {
    float y;
    asm("ex2.approx.f32 %0, %1;" : "=f"(y) : "f"(x));
    return y;
}

#define L2E 1.4426950408889634f

// ---------------------------------------------------------------------------
// K1: conv3x3x3 + bias and conv1x1x1 + bias; per-block stats partials
// ---------------------------------------------------------------------------
__global__ void k_conv(const float* __restrict__ x, const float* __restrict__ W3,
                       const float* __restrict__ b3, const float* __restrict__ W1,
                       const float* __restrict__ b1)
{
    __shared__ float sW3[432], sW1[16], sb3[4], sb1[4];
    int t = threadIdx.x;
    for (int i = t; i < 432; i += 256) sW3[i] = W3[i];
    if (t < 16)  sW1[t] = W1[t];
    if (t < 4) { sb3[t] = b3[t]; sb1[t] = b1[t]; }
    __syncthreads();

    int idx = blockIdx.x * 256 + t;
    int o  = idx / PERCH;
    int r  = idx % PERCH;
    int d  = r >> 12;
    int hw = r & 4095;
    int h  = hw >> 6;
    int w  = hw & 63;

    float acc3 = sb3[o], acc1 = sb1[o];
    #pragma unroll
    for (int i = 0; i < 4; i++) {
        const float* xi = x + i * PERCH;
        acc1 = fmaf(xi[(d << 12) + hw], sW1[o * 4 + i], acc1);
        const float* wk = sW3 + (o * 4 + i) * 27;
        #pragma unroll
        for (int kd = 0; kd < 3; kd++) {
            int zd = d + kd - 1;
            if (zd < 0 || zd > 2) continue;
            #pragma unroll
            for (int kh = 0; kh < 3; kh++) {
                int zh = h + kh - 1;
                if ((unsigned)zh > 63u) continue;
                #pragma unroll
                for (int kw = 0; kw < 3; kw++) {
                    int zw = w + kw - 1;
                    if ((unsigned)zw > 63u) continue;
                    acc3 = fmaf(xi[(zd << 12) + (zh << 6) + zw],
                                wk[kd * 9 + kh * 3 + kw], acc3);
                }
            }
        }
    }
    d_vpre[idx]  = acc3;
    d_kqpre[idx] = acc1;

    float v0 = acc3, v1 = acc3 * acc3, v2 = acc1, v3 = acc1 * acc1;
    #pragma unroll
    for (int off = 16; off; off >>= 1) {
        v0 += __shfl_down_sync(0xffffffffu, v0, off);
        v1 += __shfl_down_sync(0xffffffffu, v1, off);
        v2 += __shfl_down_sync(0xffffffffu, v2, off);
        v3 += __shfl_down_sync(0xffffffffu, v3, off);
    }
    __shared__ float sred[8][4];
    int wid = t >> 5, lane = t & 31;
    if (lane == 0) { sred[wid][0] = v0; sred[wid][1] = v1; sred[wid][2] = v2; sred[wid][3] = v3; }
    __syncthreads();
    if (t == 0) {
        float s0 = 0, s1 = 0, s2 = 0, s3 = 0;
        #pragma unroll
        for (int i = 0; i < 8; i++) { s0 += sred[i][0]; s1 += sred[i][1]; s2 += sred[i][2]; s3 += sred[i][3]; }
        int b2 = blockIdx.x % 48;
        d_part[(0 * 4 + o) * 48 + b2] = s0;
        d_part[(1 * 4 + o) * 48 + b2] = s1;
        d_part[(2 * 4 + o) * 48 + b2] = s2;
        d_part[(3 * 4 + o) * 48 + b2] = s3;
    }
}

// ---------------------------------------------------------------------------
// K2: fused stats + BN/ReLU + compaction. grid 12 x 1024 (block=slice)
// (no qmax needed — unshifted exponent downstream)
// ---------------------------------------------------------------------------
__global__ void k_prep(const float* __restrict__ g3, const float* __restrict__ be3,
                       const float* __restrict__ g1, const float* __restrict__ be1)
{
    __shared__ float scoef[4];            // {sc3, sh3, sc1, sh1} for this channel
    __shared__ float ssum[4];
    __shared__ int   soff[32];
    __shared__ float sv[32];
    __shared__ int   s_nnz, s_P;

    int s = blockIdx.x, t = threadIdx.x;
    int lane = t & 31, w = t >> 5;
    int c = s / 3;                        // channel
    int sb = s * 4096;
    int pos = t * 4;

    // issue the big loads FIRST (independent of the stats chain)
    float4 pre3 = *(const float4*)(d_vpre  + sb + pos);
    float4 pre1 = *(const float4*)(d_kqpre + sb + pos);

    // zero-init Anz partials in parallel (pass2 overwrites occupied chunks)
    if (s == 0 && t < 192) ((float*)d_AnzP)[t] = 0.f;

    // BN stats: threads 0..3 each reduce 48 partials for quantity t of channel c
    if (t < 4) {
        const float* p = d_part + (t * 4 + c) * 48;
        float a = 0.f;
        #pragma unroll
        for (int i = 0; i < 48; i++) a += p[i];
        ssum[t] = a;
    }
    __syncthreads();
    if (t == 0) {
        const float inv_n = 1.0f / 12288.0f;
        float m3  = ssum[0] * inv_n;
        float vr3 = ssum[1] * inv_n - m3 * m3;
        float sc3 = g3[c] * rsqrtf(vr3 + 1e-5f);
        float m1  = ssum[2] * inv_n;
        float vr1 = ssum[3] * inv_n - m1 * m1;
        float sc1 = g1[c] * rsqrtf(vr1 + 1e-5f);
        scoef[0] = sc3; scoef[1] = be3[c] - m3 * sc3;
        scoef[2] = sc1; scoef[3] = be1[c] - m1 * sc1;
    }
    __syncthreads();
    float sc3 = scoef[0], sh3 = scoef[1], sc1 = scoef[2], sh1 = scoef[3];

    float4 vv, qv;
    vv.x = fmaxf(fmaf(pre3.x, sc3, sh3), 0.f);
    vv.y = fmaxf(fmaf(pre3.y, sc3, sh3), 0.f);
    vv.z = fmaxf(fmaf(pre3.z, sc3, sh3), 0.f);
    vv.w = fmaxf(fmaf(pre3.w, sc3, sh3), 0.f);
    qv.x = fmaxf(fmaf(pre1.x, sc1, sh1), 0.f);
    qv.y = fmaxf(fmaf(pre1.y, sc1, sh1), 0.f);
    qv.z = fmaxf(fmaf(pre1.z, sc1, sh1), 0.f);
    qv.w = fmaxf(fmaf(pre1.w, sc1, sh1), 0.f);
    *(float4*)(d_v + sb + pos) = vv;
    *(float4*)(d_q + sb + pos) = qv;

    // compaction flags + scans
    int c0 = qv.x > 0.f, c1 = qv.y > 0.f, c2 = qv.z > 0.f, c3 = qv.w > 0.f;
    int cnt = c0 + c1 + c2 + c3;
    float vz = (c0 ? 0.f : vv.x) + (c1 ? 0.f : vv.y)
             + (c2 ? 0.f : vv.z) + (c3 ? 0.f : vv.w);

    int inc = cnt;                        // warp inclusive scan
    #pragma unroll
    for (int off = 1; off < 32; off <<= 1) {
        int n = __shfl_up_sync(0xffffffffu, inc, off);
        if (lane >= off) inc += n;
    }
    float vzr = vz;                       // warp reduce zero-v sum
    #pragma unroll
    for (int off = 16; off; off >>= 1) vzr += __shfl_down_sync(0xffffffffu, vzr, off);
    if (lane == 31) soff[w] = inc;
    if (lane == 0)  sv[w]   = vzr;
    __syncthreads();
    if (t == 0) {                         // serial deterministic warp-offset scan
        int acc = 0; float vacc = 0.f;
        #pragma unroll
        for (int i = 0; i < 32; i++) {
            int tmp = soff[i]; soff[i] = acc; acc += tmp;
            vacc += sv[i];
        }
        s_nnz = acc;
        s_P   = (acc + 127) & ~127;       // pad to multiple of 128
        d_nnz[s]  = acc;
        d_P[s]    = s_P;
        d_S0[s]   = vacc * (1.0f / 4096.0f);
    }
    __syncthreads();
    int k = soff[w] + (inc - cnt);
    if (c0) { d_qnz[sb + k] = qv.x; d_idxnz[sb + k] = pos;     d_rank[sb + pos]     = k; k++; }
    if (c1) { d_qnz[sb + k] = qv.y; d_idxnz[sb + k] = pos + 1; d_rank[sb + pos + 1] = k; k++; }
    if (c2) { d_qnz[sb + k] = qv.z; d_idxnz[sb + k] = pos + 2; d_rank[sb + pos + 2] = k; k++; }
    if (c3) { d_qnz[sb + k] = qv.w; d_idxnz[sb + k] = pos + 3; d_rank[sb + pos + 3] = k; k++; }
    for (int i = s_nnz + t; i < s_P; i += 1024) {
        d_qnz[sb + i]  = 0.f;
        d_qanz[sb + i] = make_float2(0.f, 0.f);
    }
}

// ---------------------------------------------------------------------------
// K3: pass1: 1 row/lane, 32 rows/block, 8 warp-chunks, 8-acc inner (unshifted).
// grid 1536 x 256: slice = blk>>7, rowgroup(32) = blk&127, chunk = warp
// ---------------------------------------------------------------------------
__global__ void k_pass1()
{
    int s = blockIdx.x >> 7;
    int g = blockIdx.x & 127;
    int nnz = d_nnz[s];
    if (g * 32 >= nnz) return;
    __shared__ float sq[4096];
    __shared__ float partZ[8][32];
    int t = threadIdx.x, w = t >> 5, lane = t & 31;
    int sb = s << 12;
    int P  = d_P[s];
    int P4 = P >> 2;

    float4* sq4 = (float4*)sq;
    const float4* gq4 = (const float4*)(d_qnz + sb);
    for (int j = t; j < P4; j += 256) sq4[j] = gq4[j];
    __syncthreads();

    int k = g * 32 + lane;
    float qi   = (k < P) ? sq[k] : 0.f;
    float qln  = qi * L2E;

    int P32 = P >> 5;                      // float4s per warp chunk (mult of 4)
    const float4* p = (const float4*)sq + w * P32;
    float z0 = 0, z1 = 0, z2 = 0, z3 = 0;
    float z4 = 0, z5 = 0, z6 = 0, z7 = 0;
    for (int it = P32 >> 1; it > 0; it--, p += 2) {
        float4 qa = p[0];
        float4 qb = p[1];
        z0 += ex2f_(qln * qa.x);
        z1 += ex2f_(qln * qa.y);
        z2 += ex2f_(qln * qa.z);
        z3 += ex2f_(qln * qa.w);
        z4 += ex2f_(qln * qb.x);
        z5 += ex2f_(qln * qb.y);
        z6 += ex2f_(qln * qb.z);
        z7 += ex2f_(qln * qb.w);
    }
    partZ[w][lane] = ((z0 + z1) + (z2 + z3)) + ((z4 + z5) + (z6 + z7));
    __syncthreads();
    if (w == 0 && k < nnz) {
        // unshifted: q>=0, exponents bounded (~2^30 max) — fp32-safe.
        // padding cols give 2^0=1 each; (4096-P) covers true-zero cols.
        float Z = (((partZ[0][lane] + partZ[1][lane]) + (partZ[2][lane] + partZ[3][lane]))
                +  ((partZ[4][lane] + partZ[5][lane]) + (partZ[6][lane] + partZ[7][lane])))
                + (float)(4096 - P);
        int row = d_idxnz[sb + k];
        float av = d_v[sb + row] / Z;
        d_qanz[sb + k] = make_float2(qln, av);
    }
}

// ---------------------------------------------------------------------------
// K4: pass2, 16 i-chunks, 1 row/thread, pointer-marching 8-acc inner.
// grid 6144 x 128: slice = blk>>9; chunk = (blk&511)&15; rowgroup(128) = (blk&511)>>4
// ---------------------------------------------------------------------------
__global__ void k_pass2()
{
    int s   = blockIdx.x >> 9;
    int rem = blockIdx.x & 511;
    int c   = rem & 15;
    int g   = rem >> 4;                    // [0,32)
    int nnz = d_nnz[s];
    if (g * 128 >= nnz) return;
    int P   = d_P[s];
    int P16 = P >> 4;                      // entries per chunk (mult of 8)
    __shared__ float2 sqa[256];            // up to 2 KB
    __shared__ float sanz[4];
    int t = threadIdx.x;
    int sb = s << 12;

    float4* s4 = (float4*)sqa;
    const float4* g4 = (const float4*)(d_qanz + sb + c * P16);
    int nf4 = P16 >> 1;                    // float4s in chunk (mult of 4)
    for (int j = t; j < nf4; j += 128) s4[j] = g4[j];
    __syncthreads();

    // Anz chunk partial (only g==0 blocks; data already in smem)
    if (g == 0) {
        int w = t >> 5, lane = t & 31;
        float a = 0.f;
        for (int i = t; i < P16; i += 128) a += sqa[i].y;
        #pragma unroll
        for (int off = 16; off; off >>= 1) a += __shfl_down_sync(0xffffffffu, a, off);
        if (lane == 0) sanz[w] = a;
    }

    int k = g * 128 + t;
    float qj = d_qnz[sb + ((k < nnz) ? k : 0)];
    float a0 = 0, a1 = 0, a2 = 0, a3 = 0;
    float a4 = 0, a5 = 0, a6 = 0, a7 = 0;
    const float4* p = (const float4*)sqa;
    for (int it = nf4 >> 2; it > 0; it--, p += 4) {
        float4 u0 = p[0];
        float4 u1 = p[1];
        float4 u2 = p[2];
        float4 u3 = p[3];
        a0 = fmaf(u0.y, ex2f_(u0.x * qj), a0);
        a1 = fmaf(u0.w, ex2f_(u0.z * qj), a1);
        a2 = fmaf(u1.y, ex2f_(u1.x * qj), a2);
        a3 = fmaf(u1.w, ex2f_(u1.z * qj), a3);
        a4 = fmaf(u2.y, ex2f_(u2.x * qj), a4);
        a5 = fmaf(u2.w, ex2f_(u2.z * qj), a5);
        a6 = fmaf(u3.y, ex2f_(u3.x * qj), a6);
        a7 = fmaf(u3.w, ex2f_(u3.z * qj), a7);
    }
    if (k < nnz)
        d_ppart[c * NELEM + sb + k] = ((a0 + a1) + (a2 + a3)) + ((a4 + a5) + (a6 + a7));

    if (g == 0) {
        __syncthreads();
        if (t == 0) d_AnzP[s][c] = (sanz[0] + sanz[1]) + (sanz[2] + sanz[3]);
    }
}

// ---------------------------------------------------------------------------
// K5: final — Datt inline + assemble Patt + residual. grid 64 x 256 over (c,hw)
// ---------------------------------------------------------------------------
__global__ void k_final(const float* __restrict__ x, const float* __restrict__ gama,
                        float* __restrict__ out)
{
    int tid = blockIdx.x * 256 + threadIdx.x;   // 0..16383
    int c = tid >> 12, hw = tid & 4095;
    int base = c * PERCH + hw;
    float gm = gama[0];

    float q0 = d_q[base], q1 = d_q[base + HW], q2 = d_q[base + 2 * HW];
    float v0 = d_v[base], v1 = d_v[base + HW], v2 = d_v[base + 2 * HW];

    // depth attention
    float qm = fmaxf(q0, fmaxf(q1, q2));
    float o0 = 0, o1 = 0, o2 = 0;
    {
        float ql = q0 * L2E, nm = -ql * qm;
        float e0 = ex2f_(fmaf(ql, q0, nm)), e1 = ex2f_(fmaf(ql, q1, nm)), e2 = ex2f_(fmaf(ql, q2, nm));
        float w_ = v0 / (e0 + e1 + e2);
        o0 = fmaf(w_, e0, o0); o1 = fmaf(w_, e1, o1); o2 = fmaf(w_, e2, o2);
    }
    {
        float ql = q1 * L2E, nm = -ql * qm;
        float e0 = ex2f_(fmaf(ql, q0, nm)), e1 = ex2f_(fmaf(ql, q1, nm)), e2 = ex2f_(fmaf(ql, q2, nm));
        float w_ = v1 / (e0 + e1 + e2);
        o0 = fmaf(w_, e0, o0); o1 = fmaf(w_, e1, o1); o2 = fmaf(w_, e2, o2);
    }
    {
        float ql = q2 * L2E, nm = -ql * qm;
        float e0 = ex2f_(fmaf(ql, q0, nm)), e1 = ex2f_(fmaf(ql, q1, nm)), e2 = ex2f_(fmaf(ql, q2, nm));
        float w_ = v2 / (e0 + e1 + e2);
        o0 = fmaf(w_, e0, o0); o1 = fmaf(w_, e1, o1); o2 = fmaf(w_, e2, o2);
    }

    float dat[3] = {o0, o1, o2};
    float qd[3]  = {q0, q1, q2};
    #pragma unroll
    for (int d = 0; d < 3; d++) {
        int s = c * 3 + d;
        int idx = base + d * HW;
        float patt;
        if (qd[d] > 0.f) {
            int b = (s << 12) + d_rank[idx];
            float p0 = 0.f;
            #pragma unroll
            for (int cc = 0; cc < 16; cc++) p0 += d_ppart[cc * NELEM + b];
            patt = p0;
        } else {
            float p0 = 0.f;
            #pragma unroll
            for (int cc = 0; cc < 16; cc++) p0 += d_AnzP[s][cc];
            patt = p0;
        }
        patt += d_S0[s];
        out[idx] = fmaf(gm, patt + dat[d], x[idx]);
    }
}

// ---------------------------------------------------------------------------
extern "C" void kernel_launch(void* const* d_in, const int* in_sizes, int n_in,
                              void* d_out, int out_size)
{
    const float* x    = (const float*)d_in[0];
    const float* W3   = (const float*)d_in[1];
    const float* b3   = (const float*)d_in[2];
    const float* g3   = (const float*)d_in[3];
    const float* be3  = (const float*)d_in[4];
    const float* W1   = (const float*)d_in[5];
    const float* b1   = (const float*)d_in[6];
    const float* g1   = (const float*)d_in[7];
    const float* be1  = (const float*)d_in[8];
    const float* gama = (const float*)d_in[9];
    float* out = (float*)d_out;

    k_conv <<<192,  256>>>(x, W3, b3, W1, b1);
    k_prep <<<12,  1024>>>(g3, be3, g1, be1);
    k_pass1<<<1536, 256>>>();
    k_pass2<<<6144, 128>>>();
    k_final<<<64,   256>>>(x, gama, out);
}

// round 16
// speedup vs baseline: 1.4751x; 1.0384x over previous
#include <cuda_runtime.h>

// Problem constants: N=1, C=4, D=3, H=W=64
#define NELEM 49152      // 4*3*64*64
#define HW    4096
#define PERCH 12288      // D*H*W per channel
#define XPAD  87120      // 4 * 5 * 66 * 66

__device__ float  d_xpad[XPAD];        // zero-padded x: [c][zd+1][h+1][w+1]
__device__ float  d_vpre[NELEM];
__device__ float  d_kqpre[NELEM];
__device__ float  d_part[16 * 48];     // [quant(4)*chan(4)][48 block partials]
__device__ float  d_v[NELEM];
__device__ float  d_q[NELEM];

// sparsity-compacted state (per slice of 4096)
__device__ int    d_nnz[12];
__device__ int    d_P[12];             // nnz padded up to multiple of 128
__device__ float  d_qnz[NELEM];        // compacted q values (padding = 0)
__device__ int    d_idxnz[NELEM];      // compacted k -> original pos
__device__ int    d_rank[NELEM];       // original pos -> compacted k (nz only)
__device__ float  d_S0[12];            // sum_{zero i} v_i / 4096
__device__ float  d_AnzP[12][16];      // per-chunk Anz partials
__device__ float2 d_qanz[NELEM];       // compacted {qln_i, a_i} (padding = {0,0})
__device__ float  d_ppart[16 * NELEM]; // pass2 chunk partials (compacted idx)

__device__ __forceinline__ float ex2f_(float x) {
    float y;
    asm("ex2.approx.f32 %0, %1;" : "=f"(y) : "f"(x));
    return y;
}

#define L2E 1.4426950408889634f

// ---------------------------------------------------------------------------
// K0: zero-pad x into d_xpad. grid 341 x 256
// ---------------------------------------------------------------------------
__global__ void k_pad(const float* __restrict__ x)
{
    int i = blockIdx.x * 256 + threadIdx.x;
    if (i >= XPAD) return;
    int c  = i / 21780;
    int r0 = i % 21780;
    int p  = r0 / 4356;
    int r1 = r0 % 4356;
    int row = r1 / 66;
    int col = r1 % 66;
    float val = 0.f;
    if (p >= 1 && p <= 3 && row >= 1 && row <= 64 && col >= 1 && col <= 64)
        val = x[c * PERCH + (p - 1) * 4096 + ((row - 1) << 6) + (col - 1)];
    d_xpad[i] = val;
}

// ---------------------------------------------------------------------------
// K1: branchless conv3 (padded) + conv1 + bias; per-block stats partials
// ---------------------------------------------------------------------------
__global__ void k_conv(const float* __restrict__ x, const float* __restrict__ W3,
                       const float* __restrict__ b3, const float* __restrict__ W1,
                       const float* __restrict__ b1)
{
    __shared__ float sW3[432], sW1[16], sb3[4], sb1[4];
    int t = threadIdx.x;
    for (int i = t; i < 432; i += 256) sW3[i] = W3[i];
    if (t < 16)  sW1[t] = W1[t];
    if (t < 4) { sb3[t] = b3[t]; sb1[t] = b1[t]; }
    __syncthreads();

    int idx = blockIdx.x * 256 + t;
    int o  = idx / PERCH;
    int r  = idx % PERCH;
    int d  = r >> 12;
    int hw = r & 4095;
    int h  = hw >> 6;
    int w  = hw & 63;

    float acc3 = sb3[o], acc1 = sb1[o];
    int poff = h * 66 + w;                 // (h+kh)(w+kw) base at kh=kw=0
    #pragma unroll
    for (int i = 0; i < 4; i++) {
        acc1 = fmaf(x[i * PERCH + (d << 12) + hw], sW1[o * 4 + i], acc1);
        const float* xp = d_xpad + (i * 5 + d) * 4356 + poff;
        const float* wk = sW3 + (o * 4 + i) * 27;
        #pragma unroll
        for (int kd = 0; kd < 3; kd++)
            #pragma unroll
            for (int kh = 0; kh < 3; kh++)
                #pragma unroll
                for (int kw = 0; kw < 3; kw++)
                    acc3 = fmaf(xp[kd * 4356 + kh * 66 + kw],
                                wk[kd * 9 + kh * 3 + kw], acc3);
    }
    d_vpre[idx]  = acc3;
    d_kqpre[idx] = acc1;

    float v0 = acc3, v1 = acc3 * acc3, v2 = acc1, v3 = acc1 * acc1;
    #pragma unroll
    for (int off = 16; off; off >>= 1) {
        v0 += __shfl_down_sync(0xffffffffu, v0, off);
        v1 += __shfl_down_sync(0xffffffffu, v1, off);
        v2 += __shfl_down_sync(0xffffffffu, v2, off);
        v3 += __shfl_down_sync(0xffffffffu, v3, off);
    }
    __shared__ float sred[8][4];
    int wid = t >> 5, lane = t & 31;
    if (lane == 0) { sred[wid][0] = v0; sred[wid][1] = v1; sred[wid][2] = v2; sred[wid][3] = v3; }
    __syncthreads();
    if (t == 0) {
        float s0 = 0, s1 = 0, s2 = 0, s3 = 0;
        #pragma unroll
        for (int i = 0; i < 8; i++) { s0 += sred[i][0]; s1 += sred[i][1]; s2 += sred[i][2]; s3 += sred[i][3]; }
        int b2 = blockIdx.x % 48;
        d_part[(0 * 4 + o) * 48 + b2] = s0;
        d_part[(1 * 4 + o) * 48 + b2] = s1;
        d_part[(2 * 4 + o) * 48 + b2] = s2;
        d_part[(3 * 4 + o) * 48 + b2] = s3;
    }
}

// ---------------------------------------------------------------------------
// K2: fused stats + BN/ReLU + compaction. grid 12 x 1024 (block=slice)
// ---------------------------------------------------------------------------
__global__ void k_prep(const float* __restrict__ g3, const float* __restrict__ be3,
                       const float* __restrict__ g1, const float* __restrict__ be1)
{
    __shared__ float scoef[4];
    __shared__ float ssum[4];
    __shared__ int   soff[32];
    __shared__ float sv[32];
    __shared__ int   s_nnz, s_P;

    int s = blockIdx.x, t = threadIdx.x;
    int lane = t & 31, w = t >> 5;
    int c = s / 3;                        // channel
    int sb = s * 4096;
    int pos = t * 4;

    float4 pre3 = *(const float4*)(d_vpre  + sb + pos);
    float4 pre1 = *(const float4*)(d_kqpre + sb + pos);

    if (s == 0 && t < 192) ((float*)d_AnzP)[t] = 0.f;

    if (t < 4) {
        const float* p = d_part + (t * 4 + c) * 48;
        float a = 0.f;
        #pragma unroll
        for (int i = 0; i < 48; i++) a += p[i];
        ssum[t] = a;
    }
    __syncthreads();
    if (t == 0) {
        const float inv_n = 1.0f / 12288.0f;
        float m3  = ssum[0] * inv_n;
        float vr3 = ssum[1] * inv_n - m3 * m3;
        float sc3 = g3[c] * rsqrtf(vr3 + 1e-5f);
        float m1  = ssum[2] * inv_n;
        float vr1 = ssum[3] * inv_n - m1 * m1;
        float sc1 = g1[c] * rsqrtf(vr1 + 1e-5f);
        scoef[0] = sc3; scoef[1] = be3[c] - m3 * sc3;
        scoef[2] = sc1; scoef[3] = be1[c] - m1 * sc1;
    }
    __syncthreads();
    float sc3 = scoef[0], sh3 = scoef[1], sc1 = scoef[2], sh1 = scoef[3];

    float4 vv, qv;
    vv.x = fmaxf(fmaf(pre3.x, sc3, sh3), 0.f);
    vv.y = fmaxf(fmaf(pre3.y, sc3, sh3), 0.f);
    vv.z = fmaxf(fmaf(pre3.z, sc3, sh3), 0.f);
    vv.w = fmaxf(fmaf(pre3.w, sc3, sh3), 0.f);
    qv.x = fmaxf(fmaf(pre1.x, sc1, sh1), 0.f);
    qv.y = fmaxf(fmaf(pre1.y, sc1, sh1), 0.f);
    qv.z = fmaxf(fmaf(pre1.z, sc1, sh1), 0.f);
    qv.w = fmaxf(fmaf(pre1.w, sc1, sh1), 0.f);
    *(float4*)(d_v + sb + pos) = vv;
    *(float4*)(d_q + sb + pos) = qv;

    int c0 = qv.x > 0.f, c1 = qv.y > 0.f, c2 = qv.z > 0.f, c3 = qv.w > 0.f;
    int cnt = c0 + c1 + c2 + c3;
    float vz = (c0 ? 0.f : vv.x) + (c1 ? 0.f : vv.y)
             + (c2 ? 0.f : vv.z) + (c3 ? 0.f : vv.w);

    int inc = cnt;                        // warp inclusive scan
    #pragma unroll
    for (int off = 1; off < 32; off <<= 1) {
        int n = __shfl_up_sync(0xffffffffu, inc, off);
        if (lane >= off) inc += n;
    }
    float vzr = vz;
    #pragma unroll
    for (int off = 16; off; off >>= 1) vzr += __shfl_down_sync(0xffffffffu, vzr, off);
    if (lane == 31) soff[w] = inc;
    if (lane == 0)  sv[w]   = vzr;
    __syncthreads();
    if (t == 0) {
        int acc = 0; float vacc = 0.f;
        #pragma unroll
        for (int i = 0; i < 32; i++) {
            int tmp = soff[i]; soff[i] = acc; acc += tmp;
            vacc += sv[i];
        }
        s_nnz = acc;
        s_P   = (acc + 127) & ~127;
        d_nnz[s]  = acc;
        d_P[s]    = s_P;
        d_S0[s]   = vacc * (1.0f / 4096.0f);
    }
    __syncthreads();
    int k = soff[w] + (inc - cnt);
    if (c0) { d_qnz[sb + k] = qv.x; d_idxnz[sb + k] = pos;     d_rank[sb + pos]     = k; k++; }
    if (c1) { d_qnz[sb + k] = qv.y; d_idxnz[sb + k] = pos + 1; d_rank[sb + pos + 1] = k; k++; }
    if (c2) { d_qnz[sb + k] = qv.z; d_idxnz[sb + k] = pos + 2; d_rank[sb + pos + 2] = k; k++; }
    if (c3) { d_qnz[sb + k] = qv.w; d_idxnz[sb + k] = pos + 3; d_rank[sb + pos + 3] = k; k++; }
    for (int i = s_nnz + t; i < s_P; i += 1024) {
        d_qnz[sb + i]  = 0.f;
        d_qanz[sb + i] = make_float2(0.f, 0.f);
    }
}

// ---------------------------------------------------------------------------
// K3: pass1: 512 thr, 64 rows/block (2 halves x 8 warp-chunks), unshifted.
// grid 768 x 512: slice = blk>>6, rowgroup(64) = blk&63
// warp w: chunk = w&7, half = w>>3; row = g*64 + half*32 + lane
// ---------------------------------------------------------------------------
__global__ void k_pass1()
{
    int s = blockIdx.x >> 6;
    int g = blockIdx.x & 63;
    int nnz = d_nnz[s];
    if (g * 64 >= nnz) return;
    __shared__ float sq[4096];
    __shared__ float partZ[2][8][32];
    int t = threadIdx.x, w = t >> 5, lane = t & 31;
    int chunk = w & 7, half = w >> 3;
    int sb = s << 12;
    int P  = d_P[s];
    int P4 = P >> 2;

    float4* sq4 = (float4*)sq;
    const float4* gq4 = (const float4*)(d_qnz + sb);
    for (int j = t; j < P4; j += 512) sq4[j] = gq4[j];
    __syncthreads();

    int k = g * 64 + half * 32 + lane;
    float qi   = (k < P) ? sq[k] : 0.f;
    float qln  = qi * L2E;

    int P32 = P >> 5;                      // float4s per chunk (mult of 4)
    const float4* p = (const float4*)sq + chunk * P32;
    float z0 = 0, z1 = 0, z2 = 0, z3 = 0;
    float z4 = 0, z5 = 0, z6 = 0, z7 = 0;
    for (int it = P32 >> 1; it > 0; it--, p += 2) {
        float4 qa = p[0];
        float4 qb = p[1];
        z0 += ex2f_(qln * qa.x);
        z1 += ex2f_(qln * qa.y);
        z2 += ex2f_(qln * qa.z);
        z3 += ex2f_(qln * qa.w);
        z4 += ex2f_(qln * qb.x);
        z5 += ex2f_(qln * qb.y);
        z6 += ex2f_(qln * qb.z);
        z7 += ex2f_(qln * qb.w);
    }
    partZ[half][chunk][lane] = ((z0 + z1) + (z2 + z3)) + ((z4 + z5) + (z6 + z7));
    __syncthreads();
    if (w < 2) {                           // warp w handles half w
        int kk = g * 64 + w * 32 + lane;
        if (kk < nnz) {
            float Z = (((partZ[w][0][lane] + partZ[w][1][lane]) + (partZ[w][2][lane] + partZ[w][3][lane]))
                    +  ((partZ[w][4][lane] + partZ[w][5][lane]) + (partZ[w][6][lane] + partZ[w][7][lane])))
                    + (float)(4096 - P);
            int row = d_idxnz[sb + kk];
            float av = d_v[sb + row] / Z;
            d_qanz[sb + kk] = make_float2(sq[kk] * L2E, av);
        }
    }
}

// ---------------------------------------------------------------------------
// K4: pass2, 16 i-chunks, 256 thr (256 rows/block share one chunk load).
// grid 3072 x 256: slice = blk>>8; chunk = (blk&255)&15; rowgroup(256) = (blk&255)>>4
// ---------------------------------------------------------------------------
__global__ void k_pass2()
{
    int s   = blockIdx.x >> 8;
    int rem = blockIdx.x & 255;
    int c   = rem & 15;
    int g   = rem >> 4;                    // [0,16)
    int nnz = d_nnz[s];
    if (g * 256 >= nnz) return;
    int P   = d_P[s];
    int P16 = P >> 4;                      // entries per chunk (mult of 8)
    __shared__ float2 sqa[256];            // up to 2 KB
    __shared__ float sanz[8];
    int t = threadIdx.x;
    int sb = s << 12;

    float4* s4 = (float4*)sqa;
    const float4* g4 = (const float4*)(d_qanz + sb + c * P16);
    int nf4 = P16 >> 1;                    // float4s in chunk (mult of 4)
    for (int j = t; j < nf4; j += 256) s4[j] = g4[j];
    __syncthreads();

    // Anz chunk partial (only g==0 blocks; data already in smem)
    if (g == 0) {
        int w = t >> 5, lane = t & 31;
        float a = 0.f;
        for (int i = t; i < P16; i += 256) a += sqa[i].y;
        #pragma unroll
        for (int off = 16; off; off >>= 1) a += __shfl_down_sync(0xffffffffu, a, off);
        if (lane == 0) sanz[w] = a;
    }

    int k = g * 256 + t;
    float qj = d_qnz[sb + ((k < nnz) ? k : 0)];
    float a0 = 0, a1 = 0, a2 = 0, a3 = 0;
    float a4 = 0, a5 = 0, a6 = 0, a7 = 0;
    const float4* p = (const float4*)sqa;
    for (int it = nf4 >> 2; it > 0; it--, p += 4) {
        float4 u0 = p[0];
        float4 u1 = p[1];
        float4 u2 = p[2];
        float4 u3 = p[3];
        a0 = fmaf(u0.y, ex2f_(u0.x * qj), a0);
        a1 = fmaf(u0.w, ex2f_(u0.z * qj), a1);
        a2 = fmaf(u1.y, ex2f_(u1.x * qj), a2);
        a3 = fmaf(u1.w, ex2f_(u1.z * qj), a3);
        a4 = fmaf(u2.y, ex2f_(u2.x * qj), a4);
        a5 = fmaf(u2.w, ex2f_(u2.z * qj), a5);
        a6 = fmaf(u3.y, ex2f_(u3.x * qj), a6);
        a7 = fmaf(u3.w, ex2f_(u3.z * qj), a7);
    }
    if (k < nnz)
        d_ppart[c * NELEM + sb + k] = ((a0 + a1) + (a2 + a3)) + ((a4 + a5) + (a6 + a7));

    if (g == 0) {
        __syncthreads();
        if (t == 0)
            d_AnzP[s][c] = ((sanz[0] + sanz[1]) + (sanz[2] + sanz[3]))
                         + ((sanz[4] + sanz[5]) + (sanz[6] + sanz[7]));
    }
}

// ---------------------------------------------------------------------------
// K5: final — Datt inline + assemble Patt + residual. grid 64 x 256 over (c,hw)
// ---------------------------------------------------------------------------
__global__ void k_final(const float* __restrict__ x, const float* __restrict__ gama,
                        float* __restrict__ out)
{
    int tid = blockIdx.x * 256 + threadIdx.x;   // 0..16383
    int c = tid >> 12, hw = tid & 4095;
    int base = c * PERCH + hw;
    float gm = gama[0];

    float q0 = d_q[base], q1 = d_q[base + HW], q2 = d_q[base + 2 * HW];
    float v0 = d_v[base], v1 = d_v[base + HW], v2 = d_v[base + 2 * HW];

    float qm = fmaxf(q0, fmaxf(q1, q2));
    float o0 = 0, o1 = 0, o2 = 0;
    {
        float ql = q0 * L2E, nm = -ql * qm;
        float e0 = ex2f_(fmaf(ql, q0, nm)), e1 = ex2f_(fmaf(ql, q1, nm)), e2 = ex2f_(fmaf(ql, q2, nm));
        float w_ = v0 / (e0 + e1 + e2);
        o0 = fmaf(w_, e0, o0); o1 = fmaf(w_, e1, o1); o2 = fmaf(w_, e2, o2);
    }
    {
        float ql = q1 * L2E, nm = -ql * qm;
        float e0 = ex2f_(fmaf(ql, q0, nm)), e1 = ex2f_(fmaf(ql, q1, nm)), e2 = ex2f_(fmaf(ql, q2, nm));
        float w_ = v1 / (e0 + e1 + e2);
        o0 = fmaf(w_, e0, o0); o1 = fmaf(w_, e1, o1); o2 = fmaf(w_, e2, o2);
    }
    {
        float ql = q2 * L2E, nm = -ql * qm;
        float e0 = ex2f_(fmaf(ql, q0, nm)), e1 = ex2f_(fmaf(ql, q1, nm)), e2 = ex2f_(fmaf(ql, q2, nm));
        float w_ = v2 / (e0 + e1 + e2);
        o0 = fmaf(w_, e0, o0); o1 = fmaf(w_, e1, o1); o2 = fmaf(w_, e2, o2);
    }

    float dat[3] = {o0, o1, o2};
    float qd[3]  = {q0, q1, q2};
    #pragma unroll
    for (int d = 0; d < 3; d++) {
        int s = c * 3 + d;
        int idx = base + d * HW;
        float patt;
        if (qd[d] > 0.f) {
            int b = (s << 12) + d_rank[idx];
            float p0 = 0.f;
            #pragma unroll
            for (int cc = 0; cc < 16; cc++) p0 += d_ppart[cc * NELEM + b];
            patt = p0;
        } else {
            float p0 = 0.f;
            #pragma unroll
            for (int cc = 0; cc < 16; cc++) p0 += d_AnzP[s][cc];
            patt = p0;
        }
        patt += d_S0[s];
        out[idx] = fmaf(gm, patt + dat[d], x[idx]);
    }
}

// ---------------------------------------------------------------------------
extern "C" void kernel_launch(void* const* d_in, const int* in_sizes, int n_in,
                              void* d_out, int out_size)
{
    const float* x    = (const float*)d_in[0];
    const float* W3   = (const float*)d_in[1];
    const float* b3   = (const float*)d_in[2];
    const float* g3   = (const float*)d_in[3];
    const float* be3  = (const float*)d_in[4];
    const float* W1   = (const float*)d_in[5];
    const float* b1   = (const float*)d_in[6];
    const float* g1   = (const float*)d_in[7];
    const float* be1  = (const float*)d_in[8];
    const float* gama = (const float*)d_in[9];
    float* out = (float*)d_out;

    k_pad  <<<341,  256>>>(x);
    k_conv <<<192,  256>>>(x, W3, b3, W1, b1);
    k_prep <<<12,  1024>>>(g3, be3, g1, be1);
    k_pass1<<<768,  512>>>();
    k_pass2<<<3072, 256>>>();
    k_final<<<64,   256>>>(x, gama, out);
}